// round 9
// baseline (speedup 1.0000x reference)
#include <cuda_runtime.h>
#include <cuda_fp16.h>
#include <mma.h>

using namespace nvcuda;

// Problem constants (fixed by the dataset)
#define NN 50000
#define EE 800000
#define ETOT 850000   // EE + NN self-loops
#define HH 4
#define CC 32
#define HC 128        // HH*CC
#define NBLK ((NN + 1023) / 1024)   // 49 scan blocks
#define MBLK 128                    // GEMM rows per block
#define GGRID ((NN + MBLK - 1) / MBLK)

// ---------------- scratch (device globals: allocation-free) ----------------
__device__ __align__(16) __half g_lin16[NN * HC];  // messages (fp16, gather-only)
__device__ float g_act[NN * HC];
__device__ float g_alsrc[NN * HH];
__device__ float g_aldst[NN * HH];
__device__ __align__(16) float g_gmax[12];
__device__ int   g_csrc[ETOT];
__device__ int   g_rowptr[NN + 1];
__device__ int   g_fill[NN];
__device__ int   g_bsum[64];
__device__ int   g_is64;

// ---------------- streams for fork/join inside graph capture --------------
struct StreamPack {
    cudaStream_t sA, sB;
    cudaEvent_t evFork, evA, evB;
    StreamPack() {
        cudaStreamCreateWithFlags(&sA, cudaStreamNonBlocking);
        cudaStreamCreateWithFlags(&sB, cudaStreamNonBlocking);
        cudaEventCreateWithFlags(&evFork, cudaEventDisableTiming);
        cudaEventCreateWithFlags(&evA, cudaEventDisableTiming);
        cudaEventCreateWithFlags(&evB, cudaEventDisableTiming);
    }
};
static StreamPack g_sp;

__device__ __forceinline__ void atomicMaxF(float* addr, float v) {
    if (v >= 0.f) atomicMax((int*)addr, __float_as_int(v));
    else          atomicMin((unsigned int*)addr, __float_as_uint(v));
}

__device__ __forceinline__ void split_half(float x, __half& hi, __half& lo) {
    hi = __float2half_rn(x);
    lo = __float2half_rn(x - __half2float(hi));
}

// ---------------- edge prep ----------------
__global__ void detect_kernel(const int* __restrict__ buf) {
    if (blockIdx.x == 0 && threadIdx.x == 0) {
        int orv = 0;
        #pragma unroll
        for (int i = 1; i < 64; i += 2) orv |= buf[i];
        g_is64 = (orv == 0) ? 1 : 0;
    }
    if (blockIdx.x == 0 && threadIdx.x < 12) g_gmax[threadIdx.x] = -3.0e38f;
}

__global__ void zero_fill_kernel() {
    int t = blockIdx.x * blockDim.x + threadIdx.x;
    if (t < NN) g_fill[t] = 0;
}

// degree count: decode dst directly from the input buffer
__global__ void count_kernel(const int* __restrict__ buf) {
    int t = blockIdx.x * blockDim.x + threadIdx.x;
    if (t >= ETOT) return;
    int d;
    if (t < EE) {
        d = g_is64 ? buf[2 * (EE + t)] : buf[EE + t];
    } else {
        d = t - EE;
    }
    atomicAdd(&g_fill[d], 1);
}

// ---------------- 3-phase coalesced scan ----------------
__global__ void block_sum_kernel() {
    __shared__ int ws[32];
    int tid = threadIdx.x;
    int idx = blockIdx.x * 1024 + tid;
    int v = (idx < NN) ? g_fill[idx] : 0;
    #pragma unroll
    for (int o = 16; o >= 1; o >>= 1) v += __shfl_xor_sync(0xffffffff, v, o);
    int lane = tid & 31, wid = tid >> 5;
    if (lane == 0) ws[wid] = v;
    __syncthreads();
    if (wid == 0) {
        int w = ws[lane];
        #pragma unroll
        for (int o = 16; o >= 1; o >>= 1) w += __shfl_xor_sync(0xffffffff, w, o);
        if (lane == 0) g_bsum[blockIdx.x] = w;
    }
}

__global__ void scan_bsum_kernel() {
    __shared__ int sm[64];
    int tid = threadIdx.x;
    int v = (tid < NBLK) ? g_bsum[tid] : 0;
    sm[tid] = v;
    __syncthreads();
    #pragma unroll
    for (int o = 1; o < 64; o <<= 1) {
        int t2 = (tid >= o) ? sm[tid - o] : 0;
        __syncthreads();
        sm[tid] += t2;
        __syncthreads();
    }
    if (tid < NBLK) g_bsum[tid] = sm[tid] - v;
}

__global__ void rowptr_kernel() {
    __shared__ int ws[32];
    int tid = threadIdx.x;
    int idx = blockIdx.x * 1024 + tid;
    int lane = tid & 31, wid = tid >> 5;
    int c = (idx < NN) ? g_fill[idx] : 0;
    int v = c;
    #pragma unroll
    for (int o = 1; o < 32; o <<= 1) {
        int t2 = __shfl_up_sync(0xffffffff, v, o);
        if (lane >= o) v += t2;
    }
    if (lane == 31) ws[wid] = v;
    __syncthreads();
    if (wid == 0) {
        int w = ws[lane];
        #pragma unroll
        for (int o = 1; o < 32; o <<= 1) {
            int t2 = __shfl_up_sync(0xffffffff, w, o);
            if (lane >= o) w += t2;
        }
        ws[lane] = w;
    }
    __syncthreads();
    int excl = v - c + (wid > 0 ? ws[wid - 1] : 0) + g_bsum[blockIdx.x];
    if (idx < NN) {
        g_rowptr[idx] = excl;
        g_fill[idx] = excl;
    }
    if (idx == 0) g_rowptr[NN] = ETOT;
}

// fill CSR: decode both endpoints directly from the input buffer
__global__ void csr_fill_kernel(const int* __restrict__ buf) {
    int t = blockIdx.x * blockDim.x + threadIdx.x;
    if (t >= ETOT) return;
    int s, d;
    if (t < EE) {
        if (g_is64) {
            s = buf[2 * t];
            d = buf[2 * (EE + t)];
        } else {
            s = buf[t];
            d = buf[EE + t];
        }
    } else {
        s = d = t - EE;
    }
    int pos = atomicAdd(&g_fill[d], 1);
    g_csrc[pos] = s;
}

// ---------------- tensor-core GEMM (split fp16) + fused attention logits ----
// Y = X@W. X [NN,128] fp32, W [128,OUT] fp32. Block: 256 thr, 128 rows.
// Split-fp16: hi*hi + hi*lo + lo*hi with fp32 accumulate -> fp32-class accuracy.
template<int OUT, bool FROMACT>
__global__ __launch_bounds__(256) void gemm_al_tc_kernel(
        const float* __restrict__ X, const float* __restrict__ W,
        const float* __restrict__ a_src, const float* __restrict__ a_dst,
        int gslot) {
    constexpr int KC = 32;              // k chunk
    constexpr int NT = OUT / 16;        // wmma N tiles per warp (8 or 2)
    constexpr int NH = (OUT == 128) ? 4 : 1;

    // staging (fp16 hi/lo) aliased with epilogue C buffer (fp32, 64 x OUT)
    __shared__ __align__(16) unsigned char smem_raw[32768];
    __half* Ah = (__half*)smem_raw;                 // [128][32]
    __half* Al = Ah + MBLK * KC;
    __half* Bh = Al + MBLK * KC;                    // [32][OUT] flat
    __half* Bl = Bh + KC * OUT;
    float*  Cs = (float*)smem_raw;                  // [64][OUT]
    __shared__ float smax[NH];

    const float* __restrict__ Xp = FROMACT ? g_act : X;
    const int tid = threadIdx.x;
    const int wid = tid >> 5;
    const int row0 = blockIdx.x * MBLK;

    if (tid < NH) smax[tid] = -3.0e38f;

    wmma::fragment<wmma::accumulator, 16, 16, 16, float> acc[NT];
    #pragma unroll
    for (int j = 0; j < NT; j++) wmma::fill_fragment(acc[j], 0.f);

    for (int kc = 0; kc < HC; kc += KC) {
        __syncthreads();
        // stage A chunk: 128 rows x 32 cols, split into hi/lo
        #pragma unroll
        for (int e = tid; e < MBLK * (KC / 4); e += 256) {
            int r  = e >> 3;            // 8 float4 per row
            int c4 = e & 7;
            int row = row0 + r; if (row >= NN) row = NN - 1;
            float4 v = *(const float4*)&Xp[row * HC + kc + c4 * 4];
            __half h0, l0, h1, l1, h2, l2, h3, l3;
            split_half(v.x, h0, l0); split_half(v.y, h1, l1);
            split_half(v.z, h2, l2); split_half(v.w, h3, l3);
            int o = r * KC + c4 * 4;
            *(__half2*)&Ah[o]     = __halves2half2(h0, h1);
            *(__half2*)&Ah[o + 2] = __halves2half2(h2, h3);
            *(__half2*)&Al[o]     = __halves2half2(l0, l1);
            *(__half2*)&Al[o + 2] = __halves2half2(l2, l3);
        }
        // stage B chunk: 32 k-rows x OUT cols (W already k-major)
        #pragma unroll
        for (int e = tid; e < KC * OUT / 4; e += 256) {
            float4 v = ((const float4*)(W + kc * OUT))[e];
            __half h0, l0, h1, l1, h2, l2, h3, l3;
            split_half(v.x, h0, l0); split_half(v.y, h1, l1);
            split_half(v.z, h2, l2); split_half(v.w, h3, l3);
            int o = e * 4;
            *(__half2*)&Bh[o]     = __halves2half2(h0, h1);
            *(__half2*)&Bh[o + 2] = __halves2half2(h2, h3);
            *(__half2*)&Bl[o]     = __halves2half2(l0, l1);
            *(__half2*)&Bl[o + 2] = __halves2half2(l2, l3);
        }
        __syncthreads();

        #pragma unroll
        for (int ks = 0; ks < KC / 16; ks++) {
            wmma::fragment<wmma::matrix_a, 16, 16, 16, __half, wmma::row_major> a_hi, a_lo;
            wmma::load_matrix_sync(a_hi, &Ah[wid * 16 * KC + ks * 16], KC);
            wmma::load_matrix_sync(a_lo, &Al[wid * 16 * KC + ks * 16], KC);
            #pragma unroll
            for (int j = 0; j < NT; j++) {
                wmma::fragment<wmma::matrix_b, 16, 16, 16, __half, wmma::row_major> b_hi, b_lo;
                wmma::load_matrix_sync(b_hi, &Bh[ks * 16 * OUT + j * 16], OUT);
                wmma::load_matrix_sync(b_lo, &Bl[ks * 16 * OUT + j * 16], OUT);
                wmma::mma_sync(acc[j], a_hi, b_hi, acc[j]);
                wmma::mma_sync(acc[j], a_hi, b_lo, acc[j]);
                wmma::mma_sync(acc[j], a_lo, b_hi, acc[j]);
            }
        }
    }

    // ---- epilogue: 2 phases of 64 rows; C buffer aliases dead staging smem ----
    #pragma unroll
    for (int p = 0; p < 2; p++) {
        __syncthreads();
        if ((wid >> 2) == p) {
            #pragma unroll
            for (int j = 0; j < NT; j++)
                wmma::store_matrix_sync(&Cs[(wid & 3) * 16 * OUT + j * 16], acc[j],
                                        OUT, wmma::mem_row_major);
        }
        __syncthreads();

        if (OUT == 128) {
            int rl = tid >> 2, q = tid & 3;          // 4 threads/row, quarter == head
            int row = row0 + p * 64 + rl;
            if (row < NN) {
                const float* cr = Cs + rl * OUT + q * 32;
                float ss = 0.f, sd = 0.f;
                __half2 hb[16];
                #pragma unroll
                for (int i = 0; i < 16; i++) {
                    float2 v = *(const float2*)&cr[2 * i];
                    ss += v.x * a_src[q * 32 + 2 * i] + v.y * a_src[q * 32 + 2 * i + 1];
                    sd += v.x * a_dst[q * 32 + 2 * i] + v.y * a_dst[q * 32 + 2 * i + 1];
                    hb[i] = __float22half2_rn(v);
                }
                uint4* dst = (uint4*)&g_lin16[row * HC + q * 32];
                const uint4* s4 = (const uint4*)hb;
                dst[0] = s4[0]; dst[1] = s4[1]; dst[2] = s4[2]; dst[3] = s4[3];
                g_alsrc[row * HH + q] = ss;
                g_aldst[row * HH + q] = sd;
                atomicMaxF(&smax[q], ss);
            }
        } else {
            if (tid < 64) {
                int row = row0 + p * 64 + tid;
                if (row < NN) {
                    const float* cr = Cs + tid * OUT;
                    float ss = 0.f, sd = 0.f;
                    __half2 hb[16];
                    #pragma unroll
                    for (int i = 0; i < 16; i++) {
                        float2 v = *(const float2*)&cr[2 * i];
                        ss += v.x * a_src[2 * i] + v.y * a_src[2 * i + 1];
                        sd += v.x * a_dst[2 * i] + v.y * a_dst[2 * i + 1];
                        hb[i] = __float22half2_rn(v);
                    }
                    uint4* dst = (uint4*)&g_lin16[row * CC];
                    const uint4* s4 = (const uint4*)hb;
                    dst[0] = s4[0]; dst[1] = s4[1]; dst[2] = s4[2]; dst[3] = s4[3];
                    g_alsrc[row] = ss;
                    g_aldst[row] = sd;
                    atomicMaxF(&smax[0], ss);
                }
            }
        }
    }
    __syncthreads();
    if (tid < NH) atomicMaxF(&g_gmax[gslot + tid], smax[tid]);
}

// ---------------- single-pass fused GAT aggregation (warp per dst, fp16 gather) --
__global__ __launch_bounds__(256) void gat_agg4_kernel(const float* __restrict__ b,
                                                       int gslot, int do_elu) {
    __shared__ int    ss[8][32];
    __shared__ float4 ww[8][32];

    int warp = (blockIdx.x * blockDim.x + threadIdx.x) >> 5;
    if (warp >= NN) return;
    int lane = threadIdx.x & 31;
    int wslot = (threadIdx.x >> 5) & 7;
    int d = warp;
    int start = g_rowptr[d], end = g_rowptr[d + 1];

    float4 ad = *(const float4*)&g_aldst[d * HH];
    float4 gm = *(const float4*)&g_gmax[gslot];
    float4 m;
    m.x = gm.x + ad.x; m.x = (m.x > 0.f) ? m.x : 0.2f * m.x;
    m.y = gm.y + ad.y; m.y = (m.y > 0.f) ? m.y : 0.2f * m.y;
    m.z = gm.z + ad.z; m.z = (m.z > 0.f) ? m.z : 0.2f * m.z;
    m.w = gm.w + ad.w; m.w = (m.w > 0.f) ? m.w : 0.2f * m.w;

    const int h0 = lane >> 4;
    const int h1 = 2 + h0;

    float4 denom = make_float4(0.f, 0.f, 0.f, 0.f);
    float a0x = 0.f, a0y = 0.f, a1x = 0.f, a1y = 0.f;

    for (int base = start; base < end; base += 32) {
        int i = base + lane;
        float4 w = make_float4(0.f, 0.f, 0.f, 0.f);
        int s = 0;
        if (i < end) {
            s = g_csrc[i];
            float4 v = *(const float4*)&g_alsrc[s * HH];
            v.x += ad.x; v.y += ad.y; v.z += ad.z; v.w += ad.w;
            v.x = (v.x > 0.f) ? v.x : 0.2f * v.x;
            v.y = (v.y > 0.f) ? v.y : 0.2f * v.y;
            v.z = (v.z > 0.f) ? v.z : 0.2f * v.z;
            v.w = (v.w > 0.f) ? v.w : 0.2f * v.w;
            w.x = __expf(v.x - m.x);
            w.y = __expf(v.y - m.y);
            w.z = __expf(v.z - m.z);
            w.w = __expf(v.w - m.w);
        }
        denom.x += w.x; denom.y += w.y; denom.z += w.z; denom.w += w.w;
        ss[wslot][lane] = s;
        ww[wslot][lane] = w;
        __syncwarp();
        int n = min(32, end - base);
        for (int j = 0; j < n; j++) {
            int sj = ss[wslot][j];
            const float* wjp = (const float*)&ww[wslot][j];
            float w0 = wjp[h0];
            float w1 = wjp[h1];
            const __half2* hp = (const __half2*)(g_lin16 + sj * HC);
            float2 m0 = __half22float2(hp[lane]);
            float2 m1 = __half22float2(hp[32 + lane]);
            a0x += w0 * m0.x; a0y += w0 * m0.y;
            a1x += w1 * m1.x; a1y += w1 * m1.y;
        }
        __syncwarp();
    }

    #pragma unroll
    for (int o = 16; o >= 1; o >>= 1) {
        denom.x += __shfl_xor_sync(0xffffffff, denom.x, o);
        denom.y += __shfl_xor_sync(0xffffffff, denom.y, o);
        denom.z += __shfl_xor_sync(0xffffffff, denom.z, o);
        denom.w += __shfl_xor_sync(0xffffffff, denom.w, o);
    }
    float rd0 = 1.f / ((h0 == 0 ? denom.x : denom.y) + 1e-16f);
    float rd1 = 1.f / ((h1 == 2 ? denom.z : denom.w) + 1e-16f);

    float2 b0 = *(const float2*)&b[2 * lane];
    float2 b1 = *(const float2*)&b[64 + 2 * lane];
    a0x = a0x * rd0 + b0.x;
    a0y = a0y * rd0 + b0.y;
    a1x = a1x * rd1 + b1.x;
    a1y = a1y * rd1 + b1.y;
    if (do_elu) {
        a0x = (a0x > 0.f) ? a0x : (__expf(a0x) - 1.f);
        a0y = (a0y > 0.f) ? a0y : (__expf(a0y) - 1.f);
        a1x = (a1x > 0.f) ? a1x : (__expf(a1x) - 1.f);
        a1y = (a1y > 0.f) ? a1y : (__expf(a1y) - 1.f);
    }
    float* o = g_act + d * HC;
    *(float2*)&o[2 * lane] = make_float2(a0x, a0y);
    *(float2*)&o[64 + 2 * lane] = make_float2(a1x, a1y);
}

// layer 3 (H=1) fused with classifier head + embedding write
__global__ __launch_bounds__(256) void gat_agg1_head_kernel(
        const float* __restrict__ b, const float* __restrict__ Wc,
        const float* __restrict__ bc, float* __restrict__ out) {
    __shared__ int   ss[8][32];
    __shared__ float ww[8][32];

    int warp = (blockIdx.x * blockDim.x + threadIdx.x) >> 5;
    if (warp >= NN) return;
    int lane = threadIdx.x & 31;
    int wslot = (threadIdx.x >> 5) & 7;
    int d = warp;
    int start = g_rowptr[d], end = g_rowptr[d + 1];

    float ad = g_aldst[d];
    float gm = g_gmax[8];
    float m = gm + ad; m = (m > 0.f) ? m : 0.2f * m;

    float denom = 0.f;
    float acc = 0.f;

    for (int base = start; base < end; base += 32) {
        int i = base + lane;
        float w = 0.f;
        int s = 0;
        if (i < end) {
            s = g_csrc[i];
            float v = g_alsrc[s] + ad;
            v = (v > 0.f) ? v : 0.2f * v;
            w = __expf(v - m);
        }
        denom += w;
        ss[wslot][lane] = s;
        ww[wslot][lane] = w;
        __syncwarp();
        int n = min(32, end - base);
        for (int j = 0; j < n; j++) {
            acc += ww[wslot][j] * __half2float(g_lin16[ss[wslot][j] * CC + lane]);
        }
        __syncwarp();
    }
    #pragma unroll
    for (int o = 16; o >= 1; o >>= 1)
        denom += __shfl_xor_sync(0xffffffff, denom, o);

    float h = acc / (denom + 1e-16f) + b[lane];

    out[NN * 2 + d * CC + lane] = h;

    float o0 = h * Wc[lane * 2 + 0];
    float o1 = h * Wc[lane * 2 + 1];
    #pragma unroll
    for (int o = 16; o >= 1; o >>= 1) {
        o0 += __shfl_xor_sync(0xffffffff, o0, o);
        o1 += __shfl_xor_sync(0xffffffff, o1, o);
    }
    if (lane == 0) {
        out[d * 2 + 0] = o0 + bc[0];
        out[d * 2 + 1] = o1 + bc[1];
    }
}

// ---------------- launch ----------------
extern "C" void kernel_launch(void* const* d_in, const int* in_sizes, int n_in,
                              void* d_out, int out_size) {
    const float* x   = (const float*)d_in[0];
    const int*   ei  = (const int*)d_in[1];
    const float* W1  = (const float*)d_in[2];
    const float* a1s = (const float*)d_in[3];
    const float* a1d = (const float*)d_in[4];
    const float* b1  = (const float*)d_in[5];
    const float* W2  = (const float*)d_in[6];
    const float* a2s = (const float*)d_in[7];
    const float* a2d = (const float*)d_in[8];
    const float* b2  = (const float*)d_in[9];
    const float* W3  = (const float*)d_in[10];
    const float* a3s = (const float*)d_in[11];
    const float* a3d = (const float*)d_in[12];
    const float* b3  = (const float*)d_in[13];
    const float* Wc  = (const float*)d_in[14];
    const float* bc  = (const float*)d_in[15];
    float* out = (float*)d_out;

    const int T = 256;
    const int gE = (ETOT + T - 1) / T;
    const int gN = (NN + T - 1) / T;
    const int gW = (NN * 32 + T - 1) / T;

    cudaStream_t s0 = 0;                // capture-origin stream
    cudaStream_t sA = g_sp.sA;          // CSR branch
    cudaStream_t sB = g_sp.sB;          // GEMM1 branch

    // shared prologue on the capture stream
    detect_kernel<<<1, 32, 0, s0>>>(ei);

    // fork
    cudaEventRecord(g_sp.evFork, s0);
    cudaStreamWaitEvent(sA, g_sp.evFork, 0);
    cudaStreamWaitEvent(sB, g_sp.evFork, 0);

    // ---- branch A: CSR build ----
    zero_fill_kernel<<<gN, T, 0, sA>>>();
    count_kernel<<<gE, T, 0, sA>>>(ei);
    block_sum_kernel<<<NBLK, 1024, 0, sA>>>();
    scan_bsum_kernel<<<1, 64, 0, sA>>>();
    rowptr_kernel<<<NBLK, 1024, 0, sA>>>();
    csr_fill_kernel<<<gE, T, 0, sA>>>(ei);
    cudaEventRecord(g_sp.evA, sA);

    // ---- branch B: layer-1 GEMM + attention logits (tensor cores) ----
    gemm_al_tc_kernel<128, false><<<GGRID, 256, 0, sB>>>(x, W1, a1s, a1d, 0);
    cudaEventRecord(g_sp.evB, sB);

    // join on the capture stream
    cudaStreamWaitEvent(s0, g_sp.evA, 0);
    cudaStreamWaitEvent(s0, g_sp.evB, 0);

    // ---- layer 1 aggregation ----
    gat_agg4_kernel<<<gW, T, 0, s0>>>(b1, 0, 1);

    // ---- layer 2 ----
    gemm_al_tc_kernel<128, true><<<GGRID, 256, 0, s0>>>(nullptr, W2, a2s, a2d, 4);
    gat_agg4_kernel<<<gW, T, 0, s0>>>(b2, 4, 1);

    // ---- layer 3 (heads=1) + classifier head ----
    gemm_al_tc_kernel<32, true><<<GGRID, 256, 0, s0>>>(nullptr, W3, a3s, a3d, 8);
    gat_agg1_head_kernel<<<gW, T, 0, s0>>>(b3, Wc, bc, out);
}

// round 11
// speedup vs baseline: 1.2596x; 1.2596x over previous
#include <cuda_runtime.h>
#include <cuda_fp16.h>

// Problem constants (fixed by the dataset)
#define NN 50000
#define EE 800000
#define ETOT 850000   // EE + NN self-loops
#define HH 4
#define CC 32
#define HC 128        // HH*CC
#define NBLK ((NN + 1023) / 1024)   // 49 scan blocks

// pipeline split points (block-aligned)
#define SPLIT64 25024   // 391 * 64
#define SPLIT128 25088  // 196 * 128

// ---------------- scratch (device globals: allocation-free) ----------------
// DOUBLE-BUFFERED: layer k writes buf (k&1^... ) -> L1:0, L2:1, L3:0.
// This makes GEMM(k+1) writes disjoint from agg(k) reads during overlap.
__device__ __align__(16) __half g_lin16[2][NN * HC];
__device__ float g_alsrc[2][NN * HH];
__device__ float g_aldst[2][NN * HH];
__device__ float g_act[NN * HC];
__device__ __align__(16) float g_gmax[12];
__device__ int   g_csrc[ETOT];
__device__ int   g_rowptr[NN + 1];
__device__ int   g_fill[NN];
__device__ int   g_bsum[64];
__device__ int   g_is64;

// ---------------- streams/events for fork/join + pipelining ---------------
struct StreamPack {
    cudaStream_t sA, sB;
    cudaEvent_t evFork, evA, evB, evL1h1, evG2, evL2h1, evG3;
    StreamPack() {
        cudaStreamCreateWithFlags(&sA, cudaStreamNonBlocking);
        cudaStreamCreateWithFlags(&sB, cudaStreamNonBlocking);
        cudaEventCreateWithFlags(&evFork, cudaEventDisableTiming);
        cudaEventCreateWithFlags(&evA, cudaEventDisableTiming);
        cudaEventCreateWithFlags(&evB, cudaEventDisableTiming);
        cudaEventCreateWithFlags(&evL1h1, cudaEventDisableTiming);
        cudaEventCreateWithFlags(&evG2, cudaEventDisableTiming);
        cudaEventCreateWithFlags(&evL2h1, cudaEventDisableTiming);
        cudaEventCreateWithFlags(&evG3, cudaEventDisableTiming);
    }
};
static StreamPack g_sp;

__device__ __forceinline__ void atomicMaxF(float* addr, float v) {
    if (v >= 0.f) atomicMax((int*)addr, __float_as_int(v));
    else          atomicMin((unsigned int*)addr, __float_as_uint(v));
}

// ---- packed f32x2 helpers (FFMA2 path, sm_103a) ----
__device__ __forceinline__ unsigned long long pack2(float x) {
    unsigned long long r;
    asm("mov.b64 %0, {%1, %2};" : "=l"(r) : "f"(x), "f"(x));
    return r;
}
__device__ __forceinline__ void fma2(unsigned long long& d, unsigned long long a,
                                     unsigned long long b) {
    asm("fma.rn.f32x2 %0, %1, %2, %0;" : "+l"(d) : "l"(a), "l"(b));
}
__device__ __forceinline__ float2 unpack2(unsigned long long v) {
    float lo, hi;
    asm("mov.b64 {%0, %1}, %2;" : "=f"(lo), "=f"(hi) : "l"(v));
    return make_float2(lo, hi);
}

// ---------------- edge prep ----------------
__global__ void detect_kernel(const int* __restrict__ buf) {
    if (blockIdx.x == 0 && threadIdx.x == 0) {
        int orv = 0;
        #pragma unroll
        for (int i = 1; i < 64; i += 2) orv |= buf[i];
        g_is64 = (orv == 0) ? 1 : 0;
    }
    if (blockIdx.x == 0 && threadIdx.x < 12) g_gmax[threadIdx.x] = -3.0e38f;
}

__global__ void zero_fill_kernel() {
    int t = blockIdx.x * blockDim.x + threadIdx.x;
    if (t < NN) g_fill[t] = 0;
}

// degree count: decode dst directly from the input buffer
__global__ void count_kernel(const int* __restrict__ buf) {
    int t = blockIdx.x * blockDim.x + threadIdx.x;
    if (t >= ETOT) return;
    int d;
    if (t < EE) {
        d = g_is64 ? buf[2 * (EE + t)] : buf[EE + t];
    } else {
        d = t - EE;
    }
    atomicAdd(&g_fill[d], 1);
}

// ---------------- 3-phase coalesced scan ----------------
__global__ void block_sum_kernel() {
    __shared__ int ws[32];
    int tid = threadIdx.x;
    int idx = blockIdx.x * 1024 + tid;
    int v = (idx < NN) ? g_fill[idx] : 0;
    #pragma unroll
    for (int o = 16; o >= 1; o >>= 1) v += __shfl_xor_sync(0xffffffff, v, o);
    int lane = tid & 31, wid = tid >> 5;
    if (lane == 0) ws[wid] = v;
    __syncthreads();
    if (wid == 0) {
        int w = ws[lane];
        #pragma unroll
        for (int o = 16; o >= 1; o >>= 1) w += __shfl_xor_sync(0xffffffff, w, o);
        if (lane == 0) g_bsum[blockIdx.x] = w;
    }
}

__global__ void scan_bsum_kernel() {
    __shared__ int sm[64];
    int tid = threadIdx.x;
    int v = (tid < NBLK) ? g_bsum[tid] : 0;
    sm[tid] = v;
    __syncthreads();
    #pragma unroll
    for (int o = 1; o < 64; o <<= 1) {
        int t2 = (tid >= o) ? sm[tid - o] : 0;
        __syncthreads();
        sm[tid] += t2;
        __syncthreads();
    }
    if (tid < NBLK) g_bsum[tid] = sm[tid] - v;
}

__global__ void rowptr_kernel() {
    __shared__ int ws[32];
    int tid = threadIdx.x;
    int idx = blockIdx.x * 1024 + tid;
    int lane = tid & 31, wid = tid >> 5;
    int c = (idx < NN) ? g_fill[idx] : 0;
    int v = c;
    #pragma unroll
    for (int o = 1; o < 32; o <<= 1) {
        int t2 = __shfl_up_sync(0xffffffff, v, o);
        if (lane >= o) v += t2;
    }
    if (lane == 31) ws[wid] = v;
    __syncthreads();
    if (wid == 0) {
        int w = ws[lane];
        #pragma unroll
        for (int o = 1; o < 32; o <<= 1) {
            int t2 = __shfl_up_sync(0xffffffff, w, o);
            if (lane >= o) w += t2;
        }
        ws[lane] = w;
    }
    __syncthreads();
    int excl = v - c + (wid > 0 ? ws[wid - 1] : 0) + g_bsum[blockIdx.x];
    if (idx < NN) {
        g_rowptr[idx] = excl;
        g_fill[idx] = excl;
    }
    if (idx == 0) g_rowptr[NN] = ETOT;
}

// fill CSR: decode both endpoints directly from the input buffer
__global__ void csr_fill_kernel(const int* __restrict__ buf) {
    int t = blockIdx.x * blockDim.x + threadIdx.x;
    if (t >= ETOT) return;
    int s, d;
    if (t < EE) {
        if (g_is64) {
            s = buf[2 * t];
            d = buf[2 * (EE + t)];
        } else {
            s = buf[t];
            d = buf[EE + t];
        }
    } else {
        s = d = t - EE;
    }
    int pos = atomicAdd(&g_fill[d], 1);
    g_csrc[pos] = s;
}

// ---------------- GEMM (FFMA2) + fused attention logits ----------------
// Writes messages/logits into buffer `obuf`.
template<int OUT, bool FROMACT>
__global__ __launch_bounds__(128) void gemm_al_kernel(
        const float* __restrict__ X, const float* __restrict__ W,
        const float* __restrict__ a_src, const float* __restrict__ a_dst,
        int gslot, int row_off, int obuf) {
    constexpr int NPB = (OUT == 128) ? 64 : 128;
    constexpr int CPT = (OUT == 128) ? 8 : 4;
    constexpr int CP2 = CPT / 2;
    constexpr int CGN = OUT / CPT;
    constexpr int KC  = 32;
    constexpr int NH  = (OUT == 128) ? 4 : 1;

    __shared__ __align__(16) float Xs[KC][NPB];
    __shared__ __align__(16) float Ws[KC][OUT];
    __shared__ float smax[NH];

    const float* __restrict__ Xp = FROMACT ? g_act : X;
    __half* __restrict__ lin = &g_lin16[obuf][0];
    float* __restrict__ alsrc = &g_alsrc[obuf][0];
    float* __restrict__ aldst = &g_aldst[obuf][0];

    const int tid = threadIdx.x;
    const int cg = tid % CGN;
    const int ng = tid / CGN;
    const int row0 = blockIdx.x * NPB + row_off;

    if (tid < NH) smax[tid] = -3.0e38f;

    unsigned long long acc2[8][CP2];
    #pragma unroll
    for (int i = 0; i < 8; i++)
        #pragma unroll
        for (int j = 0; j < CP2; j++) acc2[i][j] = 0ull;

    for (int kc = 0; kc < HC; kc += KC) {
        __syncthreads();
        #pragma unroll
        for (int e = tid; e < KC * NPB / 4; e += 128) {
            int n  = e / (KC / 4);
            int kq = e % (KC / 4);
            int row = row0 + n; if (row >= NN) row = NN - 1;
            float4 v = *(const float4*)&Xp[row * HC + kc + kq * 4];
            Xs[kq * 4 + 0][n] = v.x;
            Xs[kq * 4 + 1][n] = v.y;
            Xs[kq * 4 + 2][n] = v.z;
            Xs[kq * 4 + 3][n] = v.w;
        }
        #pragma unroll
        for (int e = tid; e < KC * OUT / 4; e += 128) {
            ((float4*)&Ws[0][0])[e] = ((const float4*)&W[kc * OUT])[e];
        }
        __syncthreads();

        #pragma unroll
        for (int k = 0; k < KC; k++) {
            float4 xa = *(const float4*)&Xs[k][ng * 8];
            float4 xb = *(const float4*)&Xs[k][ng * 8 + 4];
            unsigned long long xd[8];
            xd[0] = pack2(xa.x); xd[1] = pack2(xa.y);
            xd[2] = pack2(xa.z); xd[3] = pack2(xa.w);
            xd[4] = pack2(xb.x); xd[5] = pack2(xb.y);
            xd[6] = pack2(xb.z); xd[7] = pack2(xb.w);

            unsigned long long wp[CP2];
            {
                double2 w0 = *(const double2*)&Ws[k][cg * CPT];
                wp[0] = __double_as_longlong(w0.x);
                wp[1] = __double_as_longlong(w0.y);
                if (CP2 == 4) {
                    double2 w1 = *(const double2*)&Ws[k][cg * CPT + 4];
                    wp[2] = __double_as_longlong(w1.x);
                    wp[3] = __double_as_longlong(w1.y);
                }
            }
            #pragma unroll
            for (int i = 0; i < 8; i++)
                #pragma unroll
                for (int j = 0; j < CP2; j++)
                    fma2(acc2[i][j], xd[i], wp[j]);
        }
    }

    float acc[8][CPT];
    #pragma unroll
    for (int i = 0; i < 8; i++)
        #pragma unroll
        for (int j = 0; j < CP2; j++) {
            float2 v = unpack2(acc2[i][j]);
            acc[i][2 * j] = v.x;
            acc[i][2 * j + 1] = v.y;
        }

    // store messages as fp16 (half2 pairs)
    #pragma unroll
    for (int i = 0; i < 8; i++) {
        int row = row0 + ng * 8 + i;
        if (row < NN) {
            #pragma unroll
            for (int j = 0; j < CP2; j++) {
                __half2 h = __float22half2_rn(make_float2(acc[i][2 * j], acc[i][2 * j + 1]));
                *(__half2*)&lin[row * OUT + cg * CPT + 2 * j] = h;
            }
        }
    }

    // ---- fused al ----
    float asv[CPT], adv[CPT];
    {
        float4 a0 = *(const float4*)&a_src[cg * CPT];
        asv[0] = a0.x; asv[1] = a0.y; asv[2] = a0.z; asv[3] = a0.w;
        float4 d0 = *(const float4*)&a_dst[cg * CPT];
        adv[0] = d0.x; adv[1] = d0.y; adv[2] = d0.z; adv[3] = d0.w;
        if (CPT == 8) {
            float4 a1 = *(const float4*)&a_src[cg * CPT + 4];
            asv[4] = a1.x; asv[5] = a1.y; asv[6] = a1.z; asv[7] = a1.w;
            float4 d1 = *(const float4*)&a_dst[cg * CPT + 4];
            adv[4] = d1.x; adv[5] = d1.y; adv[6] = d1.z; adv[7] = d1.w;
        }
    }
    float ssp[8], sdp[8];
    #pragma unroll
    for (int i = 0; i < 8; i++) {
        float ss = 0.f, sd = 0.f;
        #pragma unroll
        for (int j = 0; j < CPT; j++) {
            ss += acc[i][j] * asv[j];
            sd += acc[i][j] * adv[j];
        }
        ssp[i] = ss; sdp[i] = sd;
    }
    #pragma unroll
    for (int i = 0; i < 8; i++) {
        ssp[i] += __shfl_xor_sync(0xffffffff, ssp[i], 1);
        sdp[i] += __shfl_xor_sync(0xffffffff, sdp[i], 1);
        ssp[i] += __shfl_xor_sync(0xffffffff, ssp[i], 2);
        sdp[i] += __shfl_xor_sync(0xffffffff, sdp[i], 2);
        if (OUT == 32) {
            ssp[i] += __shfl_xor_sync(0xffffffff, ssp[i], 4);
            sdp[i] += __shfl_xor_sync(0xffffffff, sdp[i], 4);
        }
    }
    float lmax = -3.0e38f;
    if (OUT == 128) {
        if ((cg & 3) == 0) {
            int h = cg >> 2;
            #pragma unroll
            for (int i = 0; i < 8; i++) {
                int row = row0 + ng * 8 + i;
                if (row < NN) {
                    alsrc[row * HH + h] = ssp[i];
                    aldst[row * HH + h] = sdp[i];
                    lmax = fmaxf(lmax, ssp[i]);
                }
            }
            atomicMaxF(&smax[h], lmax);
        }
    } else {
        if (cg == 0) {
            #pragma unroll
            for (int i = 0; i < 8; i++) {
                int row = row0 + ng * 8 + i;
                if (row < NN) {
                    alsrc[row] = ssp[i];
                    aldst[row] = sdp[i];
                    lmax = fmaxf(lmax, ssp[i]);
                }
            }
            atomicMaxF(&smax[0], lmax);
        }
    }
    __syncthreads();
    if (tid < NH) atomicMaxF(&g_gmax[gslot + tid], smax[tid]);
}

// ---------------- single-pass fused GAT aggregation (warp per dst, fp16 gather) --
// Reads buffer `ibuf`, writes g_act.
__global__ __launch_bounds__(256) void gat_agg4_kernel(const float* __restrict__ b,
                                                       int gslot, int ibuf,
                                                       int node_off, int node_cnt) {
    __shared__ int    ss[8][32];
    __shared__ float4 ww[8][32];

    int warp = (blockIdx.x * blockDim.x + threadIdx.x) >> 5;
    if (warp >= node_cnt) return;
    int lane = threadIdx.x & 31;
    int wslot = (threadIdx.x >> 5) & 7;
    int d = warp + node_off;
    int start = g_rowptr[d], end = g_rowptr[d + 1];

    const __half* __restrict__ lin = &g_lin16[ibuf][0];
    const float* __restrict__ alsrc = &g_alsrc[ibuf][0];

    float4 ad = *(const float4*)&g_aldst[ibuf][d * HH];
    float4 gm = *(const float4*)&g_gmax[gslot];
    float4 m;
    m.x = gm.x + ad.x; m.x = (m.x > 0.f) ? m.x : 0.2f * m.x;
    m.y = gm.y + ad.y; m.y = (m.y > 0.f) ? m.y : 0.2f * m.y;
    m.z = gm.z + ad.z; m.z = (m.z > 0.f) ? m.z : 0.2f * m.z;
    m.w = gm.w + ad.w; m.w = (m.w > 0.f) ? m.w : 0.2f * m.w;

    const int h0 = lane >> 4;
    const int h1 = 2 + h0;

    float4 denom = make_float4(0.f, 0.f, 0.f, 0.f);
    float a0x = 0.f, a0y = 0.f, a1x = 0.f, a1y = 0.f;

    for (int base = start; base < end; base += 32) {
        int i = base + lane;
        float4 w = make_float4(0.f, 0.f, 0.f, 0.f);
        int s = 0;
        if (i < end) {
            s = g_csrc[i];
            float4 v = *(const float4*)&alsrc[s * HH];
            v.x += ad.x; v.y += ad.y; v.z += ad.z; v.w += ad.w;
            v.x = (v.x > 0.f) ? v.x : 0.2f * v.x;
            v.y = (v.y > 0.f) ? v.y : 0.2f * v.y;
            v.z = (v.z > 0.f) ? v.z : 0.2f * v.z;
            v.w = (v.w > 0.f) ? v.w : 0.2f * v.w;
            w.x = __expf(v.x - m.x);
            w.y = __expf(v.y - m.y);
            w.z = __expf(v.z - m.z);
            w.w = __expf(v.w - m.w);
        }
        denom.x += w.x; denom.y += w.y; denom.z += w.z; denom.w += w.w;
        ss[wslot][lane] = s;
        ww[wslot][lane] = w;
        __syncwarp();
        int n = min(32, end - base);
        for (int j = 0; j < n; j++) {
            int sj = ss[wslot][j];
            const float* wjp = (const float*)&ww[wslot][j];
            float w0 = wjp[h0];
            float w1 = wjp[h1];
            const __half2* hp = (const __half2*)(lin + sj * HC);
            float2 m0 = __half22float2(hp[lane]);
            float2 m1 = __half22float2(hp[32 + lane]);
            a0x += w0 * m0.x; a0y += w0 * m0.y;
            a1x += w1 * m1.x; a1y += w1 * m1.y;
        }
        __syncwarp();
    }

    #pragma unroll
    for (int o = 16; o >= 1; o >>= 1) {
        denom.x += __shfl_xor_sync(0xffffffff, denom.x, o);
        denom.y += __shfl_xor_sync(0xffffffff, denom.y, o);
        denom.z += __shfl_xor_sync(0xffffffff, denom.z, o);
        denom.w += __shfl_xor_sync(0xffffffff, denom.w, o);
    }
    float rd0 = 1.f / ((h0 == 0 ? denom.x : denom.y) + 1e-16f);
    float rd1 = 1.f / ((h1 == 2 ? denom.z : denom.w) + 1e-16f);

    float2 b0 = *(const float2*)&b[2 * lane];
    float2 b1 = *(const float2*)&b[64 + 2 * lane];
    a0x = a0x * rd0 + b0.x;
    a0y = a0y * rd0 + b0.y;
    a1x = a1x * rd1 + b1.x;
    a1y = a1y * rd1 + b1.y;
    // ELU (always applied for layers 1 and 2)
    a0x = (a0x > 0.f) ? a0x : (__expf(a0x) - 1.f);
    a0y = (a0y > 0.f) ? a0y : (__expf(a0y) - 1.f);
    a1x = (a1x > 0.f) ? a1x : (__expf(a1x) - 1.f);
    a1y = (a1y > 0.f) ? a1y : (__expf(a1y) - 1.f);

    float* o = g_act + d * HC;
    *(float2*)&o[2 * lane] = make_float2(a0x, a0y);
    *(float2*)&o[64 + 2 * lane] = make_float2(a1x, a1y);
}

// layer 3 (H=1) fused with classifier head + embedding write (reads buf 0)
__global__ __launch_bounds__(256) void gat_agg1_head_kernel(
        const float* __restrict__ b, const float* __restrict__ Wc,
        const float* __restrict__ bc, float* __restrict__ out) {
    __shared__ int   ss[8][32];
    __shared__ float ww[8][32];

    int warp = (blockIdx.x * blockDim.x + threadIdx.x) >> 5;
    if (warp >= NN) return;
    int lane = threadIdx.x & 31;
    int wslot = (threadIdx.x >> 5) & 7;
    int d = warp;
    int start = g_rowptr[d], end = g_rowptr[d + 1];

    const __half* __restrict__ lin = &g_lin16[0][0];
    const float* __restrict__ alsrc = &g_alsrc[0][0];

    float ad = g_aldst[0][d];
    float gm = g_gmax[8];
    float m = gm + ad; m = (m > 0.f) ? m : 0.2f * m;

    float denom = 0.f;
    float acc = 0.f;

    for (int base = start; base < end; base += 32) {
        int i = base + lane;
        float w = 0.f;
        int s = 0;
        if (i < end) {
            s = g_csrc[i];
            float v = alsrc[s] + ad;
            v = (v > 0.f) ? v : 0.2f * v;
            w = __expf(v - m);
        }
        denom += w;
        ss[wslot][lane] = s;
        ww[wslot][lane] = w;
        __syncwarp();
        int n = min(32, end - base);
        for (int j = 0; j < n; j++) {
            acc += ww[wslot][j] * __half2float(lin[ss[wslot][j] * CC + lane]);
        }
        __syncwarp();
    }
    #pragma unroll
    for (int o = 16; o >= 1; o >>= 1)
        denom += __shfl_xor_sync(0xffffffff, denom, o);

    float h = acc / (denom + 1e-16f) + b[lane];

    out[NN * 2 + d * CC + lane] = h;

    float o0 = h * Wc[lane * 2 + 0];
    float o1 = h * Wc[lane * 2 + 1];
    #pragma unroll
    for (int o = 16; o >= 1; o >>= 1) {
        o0 += __shfl_xor_sync(0xffffffff, o0, o);
        o1 += __shfl_xor_sync(0xffffffff, o1, o);
    }
    if (lane == 0) {
        out[d * 2 + 0] = o0 + bc[0];
        out[d * 2 + 1] = o1 + bc[1];
    }
}

// ---------------- launch ----------------
extern "C" void kernel_launch(void* const* d_in, const int* in_sizes, int n_in,
                              void* d_out, int out_size) {
    const float* x   = (const float*)d_in[0];
    const int*   ei  = (const int*)d_in[1];
    const float* W1  = (const float*)d_in[2];
    const float* a1s = (const float*)d_in[3];
    const float* a1d = (const float*)d_in[4];
    const float* b1  = (const float*)d_in[5];
    const float* W2  = (const float*)d_in[6];
    const float* a2s = (const float*)d_in[7];
    const float* a2d = (const float*)d_in[8];
    const float* b2  = (const float*)d_in[9];
    const float* W3  = (const float*)d_in[10];
    const float* a3s = (const float*)d_in[11];
    const float* a3d = (const float*)d_in[12];
    const float* b3  = (const float*)d_in[13];
    const float* Wc  = (const float*)d_in[14];
    const float* bc  = (const float*)d_in[15];
    float* out = (float*)d_out;

    const int T = 256;
    const int gE = (ETOT + T - 1) / T;
    const int gN = (NN + T - 1) / T;
    const int gW = (NN * 32 + T - 1) / T;

    cudaStream_t s0 = 0;                // capture-origin stream
    cudaStream_t sA = g_sp.sA;          // CSR branch
    cudaStream_t sB = g_sp.sB;          // GEMM overlap branch

    // node-half geometry
    const int L1H1 = SPLIT64,  L1H2 = NN - SPLIT64;    // layer1->2 boundary
    const int L2H1 = SPLIT128, L2H2 = NN - SPLIT128;   // layer2->3 boundary
    const int gW_L1H1 = (L1H1 * 32 + T - 1) / T;
    const int gW_L1H2 = (L1H2 * 32 + T - 1) / T;
    const int gW_L2H1 = (L2H1 * 32 + T - 1) / T;
    const int gW_L2H2 = (L2H2 * 32 + T - 1) / T;
    const int G2H1_BLK = SPLIT64 / 64;                       // 391
    const int G2H2_BLK = (NN - SPLIT64 + 63) / 64;           // 391
    const int G3H1_BLK = SPLIT128 / 128;                     // 196
    const int G3H2_BLK = (NN - SPLIT128 + 127) / 128;        // 195

    // shared prologue on the capture stream
    detect_kernel<<<1, 32, 0, s0>>>(ei);

    // fork
    cudaEventRecord(g_sp.evFork, s0);
    cudaStreamWaitEvent(sA, g_sp.evFork, 0);
    cudaStreamWaitEvent(sB, g_sp.evFork, 0);

    // ---- branch A: CSR build ----
    zero_fill_kernel<<<gN, T, 0, sA>>>();
    count_kernel<<<gE, T, 0, sA>>>(ei);
    block_sum_kernel<<<NBLK, 1024, 0, sA>>>();
    scan_bsum_kernel<<<1, 64, 0, sA>>>();
    rowptr_kernel<<<NBLK, 1024, 0, sA>>>();
    csr_fill_kernel<<<gE, T, 0, sA>>>(ei);
    cudaEventRecord(g_sp.evA, sA);

    // ---- branch B: layer-1 GEMM + attention logits (writes buf 0) ----
    gemm_al_kernel<128, false><<<(NN + 63) / 64, 128, 0, sB>>>(x, W1, a1s, a1d, 0, 0, 0);
    cudaEventRecord(g_sp.evB, sB);

    // join on the capture stream
    cudaStreamWaitEvent(s0, g_sp.evA, 0);
    cudaStreamWaitEvent(s0, g_sp.evB, 0);

    // ---- layer-1 agg half 1 (reads buf 0); GEMM2_h1 (writes buf 1) overlaps agg half 2 ----
    gat_agg4_kernel<<<gW_L1H1, T, 0, s0>>>(b1, 0, 0, 0, L1H1);
    cudaEventRecord(g_sp.evL1h1, s0);
    cudaStreamWaitEvent(sB, g_sp.evL1h1, 0);
    gemm_al_kernel<128, true><<<G2H1_BLK, 128, 0, sB>>>(nullptr, W2, a2s, a2d, 4, 0, 1);
    cudaEventRecord(g_sp.evG2, sB);

    gat_agg4_kernel<<<gW_L1H2, T, 0, s0>>>(b1, 0, 0, SPLIT64, L1H2);
    gemm_al_kernel<128, true><<<G2H2_BLK, 128, 0, s0>>>(nullptr, W2, a2s, a2d, 4, SPLIT64, 1);
    cudaStreamWaitEvent(s0, g_sp.evG2, 0);

    // ---- layer-2 agg half 1 (reads buf 1); GEMM3_h1 (writes buf 0) overlaps agg half 2 ----
    gat_agg4_kernel<<<gW_L2H1, T, 0, s0>>>(b2, 4, 1, 0, L2H1);
    cudaEventRecord(g_sp.evL2h1, s0);
    cudaStreamWaitEvent(sB, g_sp.evL2h1, 0);
    gemm_al_kernel<32, true><<<G3H1_BLK, 128, 0, sB>>>(nullptr, W3, a3s, a3d, 8, 0, 0);
    cudaEventRecord(g_sp.evG3, sB);

    gat_agg4_kernel<<<gW_L2H2, T, 0, s0>>>(b2, 4, 1, SPLIT128, L2H2);
    gemm_al_kernel<32, true><<<G3H2_BLK, 128, 0, s0>>>(nullptr, W3, a3s, a3d, 8, SPLIT128, 0);
    cudaStreamWaitEvent(s0, g_sp.evG3, 0);

    // ---- layer 3 aggregation (heads=1, reads buf 0) + classifier head ----
    gat_agg1_head_kernel<<<gW, T, 0, s0>>>(b3, Wc, bc, out);
}